// round 10
// baseline (speedup 1.0000x reference)
#include <cuda_runtime.h>
#include <cstdint>

#define N_NET 4096
#define NPTS  512
#define PC    63
#define DC    27
#define CIN   90
#define TPB   128

#define S68 68   // stride for K=64 weight tiles (mod 32 == 4)
#define S36 36   // stride for K=32 tiles (mod 32 == 4)

struct __align__(16) Smem {
    uint32_t W0[32 * S68];    // natural k order, word63 = b0 (bias-in-K)
    uint32_t W1[32 * S36];    // natural
    uint32_t Wfa[40 * S36];   // rows 0-31 Wf, row 32 Wa, 33-39 zero
    uint32_t Wd[32 * S68];    // words0-31=feat cols, 32-57=gWd cols33-58, 58=gWd col32, 59=bd, 60-63=0
    uint32_t Wr[8 * S36];     // rows 0-2 Wr, 3-7 zero
    float b1[32];
    float bfa[34];            // [32] = ba
    float br[4];
};

#define ZWORDS (32*S68 + 32*S36 + 40*S36 + 32*S68 + 8*S36 + 32 + 34 + 4)

__device__ __forceinline__ uint32_t f2tf(float x) {      // RNA cvt: weights only
    uint32_t u;
    asm("cvt.rna.tf32.f32 %0, %1;" : "=r"(u) : "f"(x));
    return u;
}

// a0=A[g][lab0], a1=A[g+8][lab0], a2=A[g][lab1], a3=A[g+8][lab1]
// c0=D[g][2q], c1=D[g][2q+1], c2=D[g+8][2q], c3=D[g+8][2q+1]
__device__ __forceinline__ void mma_tf32(float& c0, float& c1, float& c2, float& c3,
                                         uint32_t a0, uint32_t a1, uint32_t a2, uint32_t a3,
                                         uint32_t b0, uint32_t b1) {
    asm("mma.sync.aligned.m16n8k8.row.col.f32.tf32.tf32.f32 "
        "{%0,%1,%2,%3}, {%4,%5,%6,%7}, {%8,%9}, {%0,%1,%2,%3};"
        : "+f"(c0), "+f"(c1), "+f"(c2), "+f"(c3)
        : "r"(a0), "r"(a1), "r"(a2), "r"(a3), "r"(b0), "r"(b1));
}

#define ONE_TF 0x3F800000u

// L0 A-fragments: aligned float2 from global, raw f32 bits (HMMA truncates to tf32)
__device__ __forceinline__ void load_A0(uint32_t A0[8][4],
                                        const float* __restrict__ rowA,
                                        const float* __restrict__ rowB,
                                        int q, int q2) {
    #pragma unroll
    for (int ks = 0; ks < 8; ks++) {
        const int c0 = 8 * ks + q2;
        if (ks == 7 && q == 3) {             // pair (col62, bias-one)
            A0[7][0] = __float_as_uint(rowA[62]); A0[7][1] = __float_as_uint(rowB[62]);
            A0[7][2] = ONE_TF;                    A0[7][3] = ONE_TF;
        } else {
            float2 vA = *reinterpret_cast<const float2*>(rowA + c0);
            float2 vB = *reinterpret_cast<const float2*>(rowB + c0);
            A0[ks][0] = __float_as_uint(vA.x); A0[ks][2] = __float_as_uint(vA.y);
            A0[ks][1] = __float_as_uint(vB.x); A0[ks][3] = __float_as_uint(vB.y);
        }
    }
}

// direction A-fragments, raw bits
__device__ __forceinline__ void load_AD(uint32_t AD[4][4],
                                        const float* __restrict__ rowA,
                                        const float* __restrict__ rowB,
                                        int q) {
    #pragma unroll
    for (int ks2 = 0; ks2 < 4; ks2++) {
        const int pi2 = 4 * ks2 + q;
        if (pi2 <= 12) {
            float2 vA = *reinterpret_cast<const float2*>(rowA + 64 + 2 * pi2);
            float2 vB = *reinterpret_cast<const float2*>(rowB + 64 + 2 * pi2);
            AD[ks2][0] = __float_as_uint(vA.x); AD[ks2][2] = __float_as_uint(vA.y);
            AD[ks2][1] = __float_as_uint(vB.x); AD[ks2][3] = __float_as_uint(vB.y);
        } else if (pi2 == 13) {
            AD[ks2][0] = __float_as_uint(rowA[63]); AD[ks2][1] = __float_as_uint(rowB[63]);
            AD[ks2][2] = ONE_TF;                    AD[ks2][3] = ONE_TF;
        } else {
            AD[ks2][0] = AD[ks2][1] = AD[ks2][2] = AD[ks2][3] = 0u;
        }
    }
}

__global__ __launch_bounds__(TPB, 5) void kilonerf_mma_kernel(
    const float* __restrict__ gx,
    const float* __restrict__ gW0, const float* __restrict__ gb0,
    const float* __restrict__ gW1, const float* __restrict__ gb1,
    const float* __restrict__ gWa, const float* __restrict__ gba,
    const float* __restrict__ gWf, const float* __restrict__ gbf,
    const float* __restrict__ gWd, const float* __restrict__ gbd,
    const float* __restrict__ gWr, const float* __restrict__ gbr,
    float* __restrict__ gout)
{
    extern __shared__ char smem_raw[];
    Smem& sm = *reinterpret_cast<Smem*>(smem_raw);

    const int n = blockIdx.x;
    const int t = threadIdx.x;
    const int w = t >> 5;
    const int l = t & 31;
    const int g = l >> 2;        // groupID
    const int q = l & 3;         // threadID_in_group
    const int q2 = 2 * q;

    // ---------------- zero weights+biases, then stage (natural k order, RNA tf32) ----------------
    {
        uint32_t* zp = sm.W0;
        for (int i = t; i < ZWORDS; i += TPB) zp[i] = 0u;
        __syncthreads();

        const float* p;
        p = gW0 + (size_t)n * 32 * 63;
        for (int i = t; i < 32 * 63; i += TPB) { int r = i / 63, k = i - r * 63; sm.W0[r * S68 + k] = f2tf(p[i]); }
        p = gW1 + (size_t)n * 1024;
        for (int i = t; i < 1024; i += TPB) { int r = i >> 5, k = i & 31; sm.W1[r * S36 + k] = f2tf(p[i]); }
        p = gWf + (size_t)n * 1024;
        for (int i = t; i < 1024; i += TPB) { int r = i >> 5, k = i & 31; sm.Wfa[r * S36 + k] = f2tf(p[i]); }
        p = gWd + (size_t)n * 32 * 59;
        for (int i = t; i < 32 * 59; i += TPB) {
            int r = i / 59, c = i - r * 59;
            int wd = (c < 32) ? c : ((c == 32) ? 58 : (c - 1));  // dir0 -> word58, dirs1..26 -> 32..57
            sm.Wd[r * S68 + wd] = f2tf(p[i]);
        }
        if (t < 32) {
            sm.Wfa[32 * S36 + t] = f2tf(gWa[(size_t)n * 32 + t]);   // Wa row
            sm.W0[t * S68 + 63] = f2tf(gb0[(size_t)n * 32 + t]);    // b0 at word 63
            sm.Wd[t * S68 + 59] = f2tf(gbd[(size_t)n * 32 + t]);    // bd at word 59
            sm.b1[t]  = gb1[(size_t)n * 32 + t];
            sm.bfa[t] = gbf[(size_t)n * 32 + t];
        }
        if (t >= 32 && t < 128) { int i = t - 32; int r = i >> 5, k = i & 31; sm.Wr[r * S36 + k] = f2tf(gWr[(size_t)n * 96 + i]); }
        if (t == 0) {
            sm.bfa[32] = gba[n];
            sm.br[0] = gbr[(size_t)n * 3 + 0];
            sm.br[1] = gbr[(size_t)n * 3 + 1];
            sm.br[2] = gbr[(size_t)n * 3 + 2];
        }
    }
    __syncthreads();

    const long ptg0 = (long)n * NPTS + w * 128;
    const float* __restrict__ rowA = gx + (size_t)(ptg0 + g) * CIN;
    const float* __restrict__ rowB = rowA + 8 * CIN;

    // ---- prologue: tile 0 A0 fragments ----
    uint32_t A0[8][4];
    load_A0(A0, rowA, rowB, q, q2);

    for (int tile = 0; tile < 8; tile++) {
        const long ptg = ptg0 + tile * 16;
        // next-tile pointers (clamped on last tile: re-load same tile, values unused)
        const float* __restrict__ nrowA = rowA + ((tile < 7) ? 16 * CIN : 0);
        const float* __restrict__ nrowB = nrowA + 8 * CIN;

        // ---- L0: h1 = relu(W0 @ [pos|1]) ----
        float acc[4][4];
        #pragma unroll
        for (int nt = 0; nt < 4; nt++) acc[nt][0] = acc[nt][1] = acc[nt][2] = acc[nt][3] = 0.f;
        #pragma unroll
        for (int ks = 0; ks < 8; ks++) {
            #pragma unroll
            for (int nt = 0; nt < 4; nt++) {
                uint2 b = *reinterpret_cast<const uint2*>(&sm.W0[(nt * 8 + g) * S68 + 8 * ks + q2]);
                mma_tf32(acc[nt][0], acc[nt][1], acc[nt][2], acc[nt][3],
                         A0[ks][0], A0[ks][1], A0[ks][2], A0[ks][3], b.x, b.y);
            }
        }

        // ---- prefetch NEXT tile's A0 into the same (now-dead) registers ----
        load_A0(A0, nrowA, nrowB, q, q2);

        // C-fragment == next layer's A-fragment (repack in mma-arg order), raw bits
        uint32_t h1[4][4];
        #pragma unroll
        for (int nt = 0; nt < 4; nt++) {
            h1[nt][0] = __float_as_uint(fmaxf(acc[nt][0], 0.f));   // (g,   lab0)
            h1[nt][2] = __float_as_uint(fmaxf(acc[nt][1], 0.f));   // (g,   lab1)
            h1[nt][1] = __float_as_uint(fmaxf(acc[nt][2], 0.f));   // (g+8, lab0)
            h1[nt][3] = __float_as_uint(fmaxf(acc[nt][3], 0.f));   // (g+8, lab1)
        }

        // ---- L1: h2 = relu(W1 @ h1 + b1) ----
        #pragma unroll
        for (int nt = 0; nt < 4; nt++) acc[nt][0] = acc[nt][1] = acc[nt][2] = acc[nt][3] = 0.f;
        #pragma unroll
        for (int ks = 0; ks < 4; ks++) {
            #pragma unroll
            for (int nt = 0; nt < 4; nt++) {
                uint2 b = *reinterpret_cast<const uint2*>(&sm.W1[(nt * 8 + g) * S36 + 8 * ks + q2]);
                mma_tf32(acc[nt][0], acc[nt][1], acc[nt][2], acc[nt][3],
                         h1[ks][0], h1[ks][1], h1[ks][2], h1[ks][3], b.x, b.y);
            }
        }

        // ---- CURRENT tile's direction fragments (hoisted: covered by L2 + early L3) ----
        uint32_t AD[4][4];
        load_AD(AD, rowA, rowB, q);

        uint32_t h2[4][4];
        #pragma unroll
        for (int nt = 0; nt < 4; nt++) {
            const int col = nt * 8 + q2;
            float bc0 = sm.b1[col], bc1 = sm.b1[col + 1];
            h2[nt][0] = __float_as_uint(fmaxf(acc[nt][0] + bc0, 0.f));
            h2[nt][2] = __float_as_uint(fmaxf(acc[nt][1] + bc1, 0.f));
            h2[nt][1] = __float_as_uint(fmaxf(acc[nt][2] + bc0, 0.f));
            h2[nt][3] = __float_as_uint(fmaxf(acc[nt][3] + bc1, 0.f));
        }

        // ---- L2: [feature | alpha] = Wfa @ h2 + bfa ----
        float acc5[5][4];
        #pragma unroll
        for (int nt = 0; nt < 5; nt++) acc5[nt][0] = acc5[nt][1] = acc5[nt][2] = acc5[nt][3] = 0.f;
        #pragma unroll
        for (int ks = 0; ks < 4; ks++) {
            #pragma unroll
            for (int nt = 0; nt < 5; nt++) {
                uint2 b = *reinterpret_cast<const uint2*>(&sm.Wfa[(nt * 8 + g) * S36 + 8 * ks + q2]);
                mma_tf32(acc5[nt][0], acc5[nt][1], acc5[nt][2], acc5[nt][3],
                         h2[ks][0], h2[ks][1], h2[ks][2], h2[ks][3], b.x, b.y);
            }
        }
        uint32_t ft[4][4];
        #pragma unroll
        for (int nt = 0; nt < 4; nt++) {            // feature (no relu)
            const int col = nt * 8 + q2;
            float bc0 = sm.bfa[col], bc1 = sm.bfa[col + 1];
            ft[nt][0] = __float_as_uint(acc5[nt][0] + bc0);
            ft[nt][2] = __float_as_uint(acc5[nt][1] + bc1);
            ft[nt][1] = __float_as_uint(acc5[nt][2] + bc0);
            ft[nt][3] = __float_as_uint(acc5[nt][3] + bc1);
        }
        // alpha = col 32 -> held by q==0 lanes; broadcast within group
        const float ba = sm.bfa[32];
        const float alA = __shfl_sync(0xffffffffu, acc5[4][0] + ba, l & ~3);
        const float alB = __shfl_sync(0xffffffffu, acc5[4][2] + ba, l & ~3);

        // ---- L3: hd = relu(Wd @ [feat|dirs|1]) ----
        #pragma unroll
        for (int nt = 0; nt < 4; nt++) acc[nt][0] = acc[nt][1] = acc[nt][2] = acc[nt][3] = 0.f;
        #pragma unroll
        for (int ks = 0; ks < 8; ks++) {
            uint32_t a0, a1, a2, a3;
            if (ks < 4) { a0 = ft[ks][0]; a1 = ft[ks][1]; a2 = ft[ks][2]; a3 = ft[ks][3]; }
            else        { a0 = AD[ks - 4][0]; a1 = AD[ks - 4][1]; a2 = AD[ks - 4][2]; a3 = AD[ks - 4][3]; }
            #pragma unroll
            for (int nt = 0; nt < 4; nt++) {
                uint2 b = *reinterpret_cast<const uint2*>(&sm.Wd[(nt * 8 + g) * S68 + 8 * ks + q2]);
                mma_tf32(acc[nt][0], acc[nt][1], acc[nt][2], acc[nt][3], a0, a1, a2, a3, b.x, b.y);
            }
        }
        uint32_t hd[4][4];
        #pragma unroll
        for (int nt = 0; nt < 4; nt++) {
            hd[nt][0] = __float_as_uint(fmaxf(acc[nt][0], 0.f));
            hd[nt][2] = __float_as_uint(fmaxf(acc[nt][1], 0.f));
            hd[nt][1] = __float_as_uint(fmaxf(acc[nt][2], 0.f));
            hd[nt][3] = __float_as_uint(fmaxf(acc[nt][3], 0.f));
        }

        // ---- L4: rgb = Wr @ hd + br ----
        float r0 = 0.f, r1 = 0.f, r2 = 0.f, r3 = 0.f;
        #pragma unroll
        for (int ks = 0; ks < 4; ks++) {
            uint2 b = *reinterpret_cast<const uint2*>(&sm.Wr[g * S36 + 8 * ks + q2]);
            mma_tf32(r0, r1, r2, r3, hd[ks][0], hd[ks][1], hd[ks][2], hd[ks][3], b.x, b.y);
        }

        // ---- write [rgb, alpha] ----
        float2* out2 = reinterpret_cast<float2*>(gout);
        if (q == 0) {          // cols 0,1
            out2[(ptg + g) * 2]     = make_float2(r0 + sm.br[0], r1 + sm.br[1]);
            out2[(ptg + g + 8) * 2] = make_float2(r2 + sm.br[0], r3 + sm.br[1]);
        } else if (q == 1) {   // col 2 + alpha
            out2[(ptg + g) * 2 + 1]     = make_float2(r0 + sm.br[2], alA);
            out2[(ptg + g + 8) * 2 + 1] = make_float2(r2 + sm.br[2], alB);
        }

        rowA = nrowA;
        rowB = nrowB;
    }
}

extern "C" void kernel_launch(void* const* d_in, const int* in_sizes, int n_in,
                              void* d_out, int out_size)
{
    const float* gx  = (const float*)d_in[0];
    const float* gW0 = (const float*)d_in[1];
    const float* gb0 = (const float*)d_in[2];
    const float* gW1 = (const float*)d_in[3];
    const float* gb1 = (const float*)d_in[4];
    const float* gWa = (const float*)d_in[5];
    const float* gba = (const float*)d_in[6];
    const float* gWf = (const float*)d_in[7];
    const float* gbf = (const float*)d_in[8];
    const float* gWd = (const float*)d_in[9];
    const float* gbd = (const float*)d_in[10];
    const float* gWr = (const float*)d_in[11];
    const float* gbr = (const float*)d_in[12];
    float* gout = (float*)d_out;

    const int smem_bytes = (int)sizeof(Smem);
    cudaFuncSetAttribute(kilonerf_mma_kernel,
                         cudaFuncAttributeMaxDynamicSharedMemorySize, smem_bytes);

    kilonerf_mma_kernel<<<N_NET, TPB, smem_bytes>>>(
        gx, gW0, gb0, gW1, gb1, gWa, gba, gWf, gbf, gWd, gbd, gWr, gbr, gout);
}

// round 11
// speedup vs baseline: 1.1813x; 1.1813x over previous
#include <cuda_runtime.h>
#include <cstdint>

#define N_NET 4096
#define NPTS  512
#define PC    63
#define DC    27
#define CIN   90
#define TPB   128

#define S72 72   // stride for K=64 weight tiles (mod 32 == 8 -> conflict-free uint2 @ 8ks+2q)
#define S40 40   // stride for K=32 tiles (mod 32 == 8)

struct __align__(16) Smem {
    uint32_t W0[32 * S72];    // natural k order, word63 = b0 (bias-in-K)
    uint32_t W1[32 * S40];    // natural
    uint32_t Wfa[40 * S40];   // rows 0-31 Wf, row 32 Wa, 33-39 zero
    uint32_t Wd[32 * S72];    // words0-31=feat cols, 32-57=gWd cols33-58, 58=gWd col32, 59=bd, 60-63=0
    uint32_t Wr[8 * S40];     // rows 0-2 Wr, 3-7 zero
    float b1[32];
    float bfa[34];            // [32] = ba
    float br[4];
};

#define ZWORDS (32*S72 + 32*S40 + 40*S40 + 32*S72 + 8*S40 + 32 + 34 + 4)

__device__ __forceinline__ uint32_t f2tf(float x) {      // RNA cvt: weights only
    uint32_t u;
    asm("cvt.rna.tf32.f32 %0, %1;" : "=r"(u) : "f"(x));
    return u;
}

// a0=A[g][lab0], a1=A[g+8][lab0], a2=A[g][lab1], a3=A[g+8][lab1]
// c0=D[g][2q], c1=D[g][2q+1], c2=D[g+8][2q], c3=D[g+8][2q+1]
__device__ __forceinline__ void mma_tf32(float& c0, float& c1, float& c2, float& c3,
                                         uint32_t a0, uint32_t a1, uint32_t a2, uint32_t a3,
                                         uint32_t b0, uint32_t b1) {
    asm("mma.sync.aligned.m16n8k8.row.col.f32.tf32.tf32.f32 "
        "{%0,%1,%2,%3}, {%4,%5,%6,%7}, {%8,%9}, {%0,%1,%2,%3};"
        : "+f"(c0), "+f"(c1), "+f"(c2), "+f"(c3)
        : "r"(a0), "r"(a1), "r"(a2), "r"(a3), "r"(b0), "r"(b1));
}

#define ONE_TF 0x3F800000u

__global__ __launch_bounds__(TPB, 6) void kilonerf_mma_kernel(
    const float* __restrict__ gx,
    const float* __restrict__ gW0, const float* __restrict__ gb0,
    const float* __restrict__ gW1, const float* __restrict__ gb1,
    const float* __restrict__ gWa, const float* __restrict__ gba,
    const float* __restrict__ gWf, const float* __restrict__ gbf,
    const float* __restrict__ gWd, const float* __restrict__ gbd,
    const float* __restrict__ gWr, const float* __restrict__ gbr,
    float* __restrict__ gout)
{
    extern __shared__ char smem_raw[];
    Smem& sm = *reinterpret_cast<Smem*>(smem_raw);

    const int n = blockIdx.x;
    const int t = threadIdx.x;
    const int w = t >> 5;
    const int l = t & 31;
    const int g = l >> 2;        // groupID
    const int q = l & 3;         // threadID_in_group
    const int q2 = 2 * q;

    // ---------------- zero weights+biases, then stage (natural k order, RNA tf32) ----------------
    {
        uint32_t* zp = sm.W0;
        for (int i = t; i < ZWORDS; i += TPB) zp[i] = 0u;
        __syncthreads();

        const float* p;
        p = gW0 + (size_t)n * 32 * 63;
        for (int i = t; i < 32 * 63; i += TPB) { int r = i / 63, k = i - r * 63; sm.W0[r * S72 + k] = f2tf(p[i]); }
        p = gW1 + (size_t)n * 1024;
        for (int i = t; i < 1024; i += TPB) { int r = i >> 5, k = i & 31; sm.W1[r * S40 + k] = f2tf(p[i]); }
        p = gWf + (size_t)n * 1024;
        for (int i = t; i < 1024; i += TPB) { int r = i >> 5, k = i & 31; sm.Wfa[r * S40 + k] = f2tf(p[i]); }
        p = gWd + (size_t)n * 32 * 59;
        for (int i = t; i < 32 * 59; i += TPB) {
            int r = i / 59, c = i - r * 59;
            int wd = (c < 32) ? c : ((c == 32) ? 58 : (c - 1));  // dir0 -> word58, dirs1..26 -> 32..57
            sm.Wd[r * S72 + wd] = f2tf(p[i]);
        }
        if (t < 32) {
            sm.Wfa[32 * S40 + t] = f2tf(gWa[(size_t)n * 32 + t]);   // Wa row
            sm.W0[t * S72 + 63] = f2tf(gb0[(size_t)n * 32 + t]);    // b0 at word 63
            sm.Wd[t * S72 + 59] = f2tf(gbd[(size_t)n * 32 + t]);    // bd at word 59
            sm.b1[t]  = gb1[(size_t)n * 32 + t];
            sm.bfa[t] = gbf[(size_t)n * 32 + t];
        }
        if (t >= 32 && t < 128) { int i = t - 32; int r = i >> 5, k = i & 31; sm.Wr[r * S40 + k] = f2tf(gWr[(size_t)n * 96 + i]); }
        if (t == 0) {
            sm.bfa[32] = gba[n];
            sm.br[0] = gbr[(size_t)n * 3 + 0];
            sm.br[1] = gbr[(size_t)n * 3 + 1];
            sm.br[2] = gbr[(size_t)n * 3 + 2];
        }
    }
    __syncthreads();

    for (int tile = 0; tile < 8; tile++) {
        const long ptg = (long)n * NPTS + w * 128 + tile * 16;
        const float* __restrict__ rowA = gx + (size_t)(ptg + g) * CIN;
        const float* __restrict__ rowB = rowA + 8 * CIN;

        // ---- L0 A-fragments: aligned float2 from global, RAW f32 bits (HMMA truncates) ----
        uint32_t A0[8][4];
        #pragma unroll
        for (int ks = 0; ks < 8; ks++) {
            const int c0 = 8 * ks + q2;
            if (ks == 7 && q == 3) {             // pair (col62, bias-one)
                A0[7][0] = __float_as_uint(rowA[62]); A0[7][1] = __float_as_uint(rowB[62]);
                A0[7][2] = ONE_TF;                    A0[7][3] = ONE_TF;
            } else {
                float2 vA = *reinterpret_cast<const float2*>(rowA + c0);
                float2 vB = *reinterpret_cast<const float2*>(rowB + c0);
                A0[ks][0] = __float_as_uint(vA.x); A0[ks][2] = __float_as_uint(vA.y);
                A0[ks][1] = __float_as_uint(vB.x); A0[ks][3] = __float_as_uint(vB.y);
            }
        }

        // ---- L0: h1 = relu(W0 @ [pos|1]) ----
        float acc[4][4];
        #pragma unroll
        for (int nt = 0; nt < 4; nt++) acc[nt][0] = acc[nt][1] = acc[nt][2] = acc[nt][3] = 0.f;
        #pragma unroll
        for (int ks = 0; ks < 8; ks++) {
            #pragma unroll
            for (int nt = 0; nt < 4; nt++) {
                uint2 b = *reinterpret_cast<const uint2*>(&sm.W0[(nt * 8 + g) * S72 + 8 * ks + q2]);
                mma_tf32(acc[nt][0], acc[nt][1], acc[nt][2], acc[nt][3],
                         A0[ks][0], A0[ks][1], A0[ks][2], A0[ks][3], b.x, b.y);
            }
        }
        // C-fragment == next layer's A-fragment (repack in mma-arg order), raw bits
        uint32_t h1[4][4];
        #pragma unroll
        for (int nt = 0; nt < 4; nt++) {
            h1[nt][0] = __float_as_uint(fmaxf(acc[nt][0], 0.f));   // (g,   lab0)
            h1[nt][2] = __float_as_uint(fmaxf(acc[nt][1], 0.f));   // (g,   lab1)
            h1[nt][1] = __float_as_uint(fmaxf(acc[nt][2], 0.f));   // (g+8, lab0)
            h1[nt][3] = __float_as_uint(fmaxf(acc[nt][3], 0.f));   // (g+8, lab1)
        }

        // ---- L1: h2 = relu(W1 @ h1 + b1) ----
        #pragma unroll
        for (int nt = 0; nt < 4; nt++) acc[nt][0] = acc[nt][1] = acc[nt][2] = acc[nt][3] = 0.f;
        #pragma unroll
        for (int ks = 0; ks < 4; ks++) {
            #pragma unroll
            for (int nt = 0; nt < 4; nt++) {
                uint2 b = *reinterpret_cast<const uint2*>(&sm.W1[(nt * 8 + g) * S40 + 8 * ks + q2]);
                mma_tf32(acc[nt][0], acc[nt][1], acc[nt][2], acc[nt][3],
                         h1[ks][0], h1[ks][1], h1[ks][2], h1[ks][3], b.x, b.y);
            }
        }
        uint32_t h2[4][4];
        #pragma unroll
        for (int nt = 0; nt < 4; nt++) {
            const int col = nt * 8 + q2;
            float bc0 = sm.b1[col], bc1 = sm.b1[col + 1];
            h2[nt][0] = __float_as_uint(fmaxf(acc[nt][0] + bc0, 0.f));
            h2[nt][2] = __float_as_uint(fmaxf(acc[nt][1] + bc1, 0.f));
            h2[nt][1] = __float_as_uint(fmaxf(acc[nt][2] + bc0, 0.f));
            h2[nt][3] = __float_as_uint(fmaxf(acc[nt][3] + bc1, 0.f));
        }

        // ---- L2: [feature | alpha] = Wfa @ h2 + bfa ----
        float acc5[5][4];
        #pragma unroll
        for (int nt = 0; nt < 5; nt++) acc5[nt][0] = acc5[nt][1] = acc5[nt][2] = acc5[nt][3] = 0.f;
        #pragma unroll
        for (int ks = 0; ks < 4; ks++) {
            #pragma unroll
            for (int nt = 0; nt < 5; nt++) {
                uint2 b = *reinterpret_cast<const uint2*>(&sm.Wfa[(nt * 8 + g) * S40 + 8 * ks + q2]);
                mma_tf32(acc5[nt][0], acc5[nt][1], acc5[nt][2], acc5[nt][3],
                         h2[ks][0], h2[ks][1], h2[ks][2], h2[ks][3], b.x, b.y);
            }
        }
        uint32_t ft[4][4];
        #pragma unroll
        for (int nt = 0; nt < 4; nt++) {            // feature (no relu)
            const int col = nt * 8 + q2;
            float bc0 = sm.bfa[col], bc1 = sm.bfa[col + 1];
            ft[nt][0] = __float_as_uint(acc5[nt][0] + bc0);
            ft[nt][2] = __float_as_uint(acc5[nt][1] + bc1);
            ft[nt][1] = __float_as_uint(acc5[nt][2] + bc0);
            ft[nt][3] = __float_as_uint(acc5[nt][3] + bc1);
        }
        // alpha = col 32 -> held by q==0 lanes; broadcast within group
        const float ba = sm.bfa[32];
        const float alA = __shfl_sync(0xffffffffu, acc5[4][0] + ba, l & ~3);
        const float alB = __shfl_sync(0xffffffffu, acc5[4][2] + ba, l & ~3);

        // ---- direction A-fragments (after L2: short live range), raw bits ----
        uint32_t AD[4][4];
        #pragma unroll
        for (int ks2 = 0; ks2 < 4; ks2++) {
            const int pi2 = 4 * ks2 + q;
            if (pi2 <= 12) {
                float2 vA = *reinterpret_cast<const float2*>(rowA + 64 + 2 * pi2);
                float2 vB = *reinterpret_cast<const float2*>(rowB + 64 + 2 * pi2);
                AD[ks2][0] = __float_as_uint(vA.x); AD[ks2][2] = __float_as_uint(vA.y);
                AD[ks2][1] = __float_as_uint(vB.x); AD[ks2][3] = __float_as_uint(vB.y);
            } else if (pi2 == 13) {
                AD[ks2][0] = __float_as_uint(rowA[63]); AD[ks2][1] = __float_as_uint(rowB[63]);
                AD[ks2][2] = ONE_TF;                    AD[ks2][3] = ONE_TF;
            } else {
                AD[ks2][0] = AD[ks2][1] = AD[ks2][2] = AD[ks2][3] = 0u;
            }
        }

        // ---- L3: hd = relu(Wd @ [feat|dirs|1]) ----
        #pragma unroll
        for (int nt = 0; nt < 4; nt++) acc[nt][0] = acc[nt][1] = acc[nt][2] = acc[nt][3] = 0.f;
        #pragma unroll
        for (int ks = 0; ks < 8; ks++) {
            uint32_t a0, a1, a2, a3;
            if (ks < 4) { a0 = ft[ks][0]; a1 = ft[ks][1]; a2 = ft[ks][2]; a3 = ft[ks][3]; }
            else        { a0 = AD[ks - 4][0]; a1 = AD[ks - 4][1]; a2 = AD[ks - 4][2]; a3 = AD[ks - 4][3]; }
            #pragma unroll
            for (int nt = 0; nt < 4; nt++) {
                uint2 b = *reinterpret_cast<const uint2*>(&sm.Wd[(nt * 8 + g) * S72 + 8 * ks + q2]);
                mma_tf32(acc[nt][0], acc[nt][1], acc[nt][2], acc[nt][3], a0, a1, a2, a3, b.x, b.y);
            }
        }
        uint32_t hd[4][4];
        #pragma unroll
        for (int nt = 0; nt < 4; nt++) {
            hd[nt][0] = __float_as_uint(fmaxf(acc[nt][0], 0.f));
            hd[nt][2] = __float_as_uint(fmaxf(acc[nt][1], 0.f));
            hd[nt][1] = __float_as_uint(fmaxf(acc[nt][2], 0.f));
            hd[nt][3] = __float_as_uint(fmaxf(acc[nt][3], 0.f));
        }

        // ---- L4: rgb = Wr @ hd + br ----
        float r0 = 0.f, r1 = 0.f, r2 = 0.f, r3 = 0.f;
        #pragma unroll
        for (int ks = 0; ks < 4; ks++) {
            uint2 b = *reinterpret_cast<const uint2*>(&sm.Wr[g * S40 + 8 * ks + q2]);
            mma_tf32(r0, r1, r2, r3, hd[ks][0], hd[ks][1], hd[ks][2], hd[ks][3], b.x, b.y);
        }

        // ---- write [rgb, alpha] ----
        float2* out2 = reinterpret_cast<float2*>(gout);
        if (q == 0) {          // cols 0,1
            out2[(ptg + g) * 2]     = make_float2(r0 + sm.br[0], r1 + sm.br[1]);
            out2[(ptg + g + 8) * 2] = make_float2(r2 + sm.br[0], r3 + sm.br[1]);
        } else if (q == 1) {   // col 2 + alpha
            out2[(ptg + g) * 2 + 1]     = make_float2(r0 + sm.br[2], alA);
            out2[(ptg + g + 8) * 2 + 1] = make_float2(r2 + sm.br[2], alB);
        }
    }
}

extern "C" void kernel_launch(void* const* d_in, const int* in_sizes, int n_in,
                              void* d_out, int out_size)
{
    const float* gx  = (const float*)d_in[0];
    const float* gW0 = (const float*)d_in[1];
    const float* gb0 = (const float*)d_in[2];
    const float* gW1 = (const float*)d_in[3];
    const float* gb1 = (const float*)d_in[4];
    const float* gWa = (const float*)d_in[5];
    const float* gba = (const float*)d_in[6];
    const float* gWf = (const float*)d_in[7];
    const float* gbf = (const float*)d_in[8];
    const float* gWd = (const float*)d_in[9];
    const float* gbd = (const float*)d_in[10];
    const float* gWr = (const float*)d_in[11];
    const float* gbr = (const float*)d_in[12];
    float* gout = (float*)d_out;

    const int smem_bytes = (int)sizeof(Smem);
    cudaFuncSetAttribute(kilonerf_mma_kernel,
                         cudaFuncAttributeMaxDynamicSharedMemorySize, smem_bytes);

    kilonerf_mma_kernel<<<N_NET, TPB, smem_bytes>>>(
        gx, gW0, gb0, gW1, gb1, gWa, gba, gWf, gbf, gWd, gbd, gWr, gbr, gout);
}